// round 1
// baseline (speedup 1.0000x reference)
#include <cuda_runtime.h>
#include <cuda_bf16.h>
#include <math.h>

#define NN 50000
#define EE 800000
#define ET (EE + NN)   // edges + self loops
#define FIN0 128
#define FOUT 256

// ---------------- scratch (device globals; no allocation allowed) ----------------
__device__ float d_T1[128 * 512];     // weight_d @ H_d_base
__device__ float d_M[128 * 16];       // combined dual weight
__device__ int   d_deg[NN];
__device__ int   d_rowoff[NN + 1];
__device__ int   d_cursor[NN];
__device__ float d_dis[NN];
__device__ int   d_csr[ET];
__device__ float d_xw[NN * 16];
__device__ float d_dual[NN * 16];
__device__ float d_h0[NN * 16];
__device__ float d_h1[NN * 256];      // per-layer transformed features
__device__ float d_bufA[NN * 256];
__device__ float d_bufB[NN * 256];
__device__ float d_sa[NN * 16];
__device__ float d_da[NN * 16];

// ---------------- init ----------------
__global__ void k_init() {
    int i = blockIdx.x * blockDim.x + threadIdx.x;
    if (i < NN) { d_deg[i] = 1; d_cursor[i] = 0; }   // deg starts at 1 (self loop)
}

// ---------------- combined dual weight: M = Wd @ Hd @ Wr ----------------
__global__ void k_gemm1(const float* __restrict__ wd, const float* __restrict__ hd) {
    int idx = blockIdx.x * blockDim.x + threadIdx.x;  // 128*512
    if (idx >= 128 * 512) return;
    int i = idx >> 9, j = idx & 511;
    float a = 0.f;
    for (int k = 0; k < 512; k++) a += wd[i * 512 + k] * hd[k * 512 + j];
    d_T1[idx] = a;
}

__global__ void k_gemm2(const float* __restrict__ wr) {
    int idx = blockIdx.x * blockDim.x + threadIdx.x;  // 128*16
    if (idx >= 128 * 16) return;
    int i = idx >> 4, j = idx & 15;
    float a = 0.f;
    for (int k = 0; k < 512; k++) a += d_T1[i * 512 + k] * wr[k * 16 + j];
    d_M[idx] = a;
}

// ---------------- degree count / scan / scatter (CSR by dst) ----------------
__global__ void k_count(const int* __restrict__ dst) {
    int e = blockIdx.x * blockDim.x + threadIdx.x;
    if (e < EE) atomicAdd(&d_deg[dst[e]], 1);
}

__global__ void k_scan() {
    __shared__ int s[1024];
    __shared__ int carry;
    if (threadIdx.x == 0) { carry = 0; d_rowoff[0] = 0; }
    __syncthreads();
    for (int base = 0; base < NN; base += 1024) {
        int i = base + threadIdx.x;
        int v = (i < NN) ? d_deg[i] : 0;
        s[threadIdx.x] = v;
        __syncthreads();
        for (int off = 1; off < 1024; off <<= 1) {
            int t = (threadIdx.x >= off) ? s[threadIdx.x - off] : 0;
            __syncthreads();
            s[threadIdx.x] += t;
            __syncthreads();
        }
        if (i < NN) d_rowoff[i + 1] = carry + s[threadIdx.x];
        __syncthreads();
        if (threadIdx.x == 0) carry += s[1023];
        __syncthreads();
    }
}

__global__ void k_dis() {
    int i = blockIdx.x * blockDim.x + threadIdx.x;
    if (i < NN) d_dis[i] = rsqrtf((float)d_deg[i]);
}

__global__ void k_scatter(const int* __restrict__ ei) {
    int e = blockIdx.x * blockDim.x + threadIdx.x;
    if (e >= ET) return;
    int s, dd;
    if (e < EE) { s = ei[e]; dd = ei[EE + e]; }
    else        { s = dd = e - EE; }
    int p = atomicAdd(&d_cursor[dd], 1);
    d_csr[d_rowoff[dd] + p] = s;
}

// ---------------- GCN feature transform + dual (fused) ----------------
__global__ void k_xw_dual(const float* __restrict__ x, const float* __restrict__ Wg) {
    int idx = blockIdx.x * blockDim.x + threadIdx.x;  // NN*16
    if (idx >= NN * 16) return;
    int n = idx >> 4, j = idx & 15;
    float a = 0.f, b = 0.f;
    const float* xr = x + n * FIN0;
    for (int k = 0; k < FIN0; k++) {
        float xv = xr[k];
        a += xv * Wg[k * 16 + j];
        b += xv * d_M[k * 16 + j];
    }
    d_xw[idx] = a;
    d_dual[idx] = b;
}

// ---------------- GCN aggregation + dual + elu -> h0 ----------------
__global__ void k_gcn_agg(const float* __restrict__ bg) {
    int g = (blockIdx.x * blockDim.x + threadIdx.x) >> 4;
    int j = threadIdx.x & 15;
    if (g >= NN) return;
    int beg = d_rowoff[g], end = d_rowoff[g + 1];
    float acc = 0.f;
    for (int e = beg; e < end; e++) {
        int s = d_csr[e];
        acc += d_dis[s] * d_xw[s * 16 + j];
    }
    float v = acc * d_dis[g] + bg[j] + d_dual[g * 16 + j];
    d_h0[g * 16 + j] = v > 0.f ? v : (expf(v) - 1.f);
}

// ---------------- GAT transform: h1 = hin @ W, sa/da attention dots ----------------
template <int FIN>
__global__ void k_transform(const float* __restrict__ hin, const float* __restrict__ W,
                            const float* __restrict__ asrc, const float* __restrict__ adst) {
    __shared__ float s[8][FIN];
    int nb = blockIdx.x * 8;
    int tid = threadIdx.x;  // 256
    for (int t = tid; t < 8 * FIN; t += 256) {
        int r = t / FIN, c = t % FIN;
        int n = nb + r;
        s[r][c] = (n < NN) ? hin[n * FIN + c] : 0.f;
    }
    __syncthreads();
    float acc[8];
#pragma unroll
    for (int r = 0; r < 8; r++) acc[r] = 0.f;
    for (int k = 0; k < FIN; k++) {
        float w = W[k * 256 + tid];
#pragma unroll
        for (int r = 0; r < 8; r++) acc[r] += s[r][k] * w;
    }
    float as_ = asrc[tid], ad_ = adst[tid];
#pragma unroll
    for (int r = 0; r < 8; r++) {
        int n = nb + r;
        if (n >= NN) break;   // uniform within block
        d_h1[n * 256 + tid] = acc[r];
        float vs = acc[r] * as_, vd = acc[r] * ad_;
#pragma unroll
        for (int off = 8; off >= 1; off >>= 1) {
            vs += __shfl_down_sync(0xffffffffu, vs, off, 16);
            vd += __shfl_down_sync(0xffffffffu, vd, off, 16);
        }
        if ((tid & 15) == 0) {
            d_sa[n * 16 + (tid >> 4)] = vs;
            d_da[n * 16 + (tid >> 4)] = vd;
        }
    }
}

// ---------------- GAT aggregation: per-dst softmax + weighted sum + bias + elu ----------------
__global__ void k_gat_agg(const float* __restrict__ b, float* __restrict__ out) {
    int n = (blockIdx.x * blockDim.x + threadIdx.x) >> 5;
    if (n >= NN) return;
    int lane = threadIdx.x & 31;
    float da_l = (lane < 16) ? d_da[n * 16 + lane] : 0.f;
    int beg = d_rowoff[n], end = d_rowoff[n + 1];

    // pass 1: per-head max (lanes 0..15 hold head = lane)
    float m = -1e30f;
    for (int e = beg; e < end; e++) {
        int s = d_csr[e];
        if (lane < 16) {
            float l = d_sa[s * 16 + lane] + da_l;
            l = l > 0.f ? l : 0.2f * l;
            m = fmaxf(m, l);
        }
    }
    float mh = __shfl_sync(0xffffffffu, m, lane >> 1);  // lane owns head lane/2

    // pass 2: exp-sum + weighted accumulate (lane owns channels [8*lane, 8*lane+8))
    float z = 0.f;
    float acc[8];
#pragma unroll
    for (int i = 0; i < 8; i++) acc[i] = 0.f;
    for (int e = beg; e < end; e++) {
        int s = d_csr[e];
        float l = 0.f;
        if (lane < 16) {
            l = d_sa[s * 16 + lane] + da_l;
            l = l > 0.f ? l : 0.2f * l;
        }
        float ev = expf(__shfl_sync(0xffffffffu, l, lane >> 1) - mh);
        z += ev;
        const float4* hp = (const float4*)(d_h1 + s * 256 + lane * 8);
        float4 v0 = hp[0], v1 = hp[1];
        acc[0] += ev * v0.x; acc[1] += ev * v0.y; acc[2] += ev * v0.z; acc[3] += ev * v0.w;
        acc[4] += ev * v1.x; acc[5] += ev * v1.y; acc[6] += ev * v1.z; acc[7] += ev * v1.w;
    }
    float invz = 1.f / (z + 1e-16f);
#pragma unroll
    for (int i = 0; i < 8; i++) {
        float v = acc[i] * invz + b[lane * 8 + i];
        out[n * 256 + lane * 8 + i] = v > 0.f ? v : (expf(v) - 1.f);
    }
}

// ---------------- final: concat(h[user], h[item]) @ Wdnn -> log_softmax ----------------
__global__ void k_final(const float* __restrict__ h, const int* __restrict__ ui,
                        const int* __restrict__ ii, const float* __restrict__ Wd,
                        float* __restrict__ out) {
    int p = (blockIdx.x * blockDim.x + threadIdx.x) >> 5;
    if (p >= 1024) return;
    int lane = threadIdx.x & 31;
    int u = ui[p], it = ii[p];
    float a0 = 0.f, a1 = 0.f;
    for (int k = lane; k < 256; k += 32) {
        float v = h[u * 256 + k];
        a0 += v * Wd[k * 2 + 0];
        a1 += v * Wd[k * 2 + 1];
        float w = h[it * 256 + k];
        a0 += w * Wd[(256 + k) * 2 + 0];
        a1 += w * Wd[(256 + k) * 2 + 1];
    }
#pragma unroll
    for (int off = 16; off >= 1; off >>= 1) {
        a0 += __shfl_down_sync(0xffffffffu, a0, off);
        a1 += __shfl_down_sync(0xffffffffu, a1, off);
    }
    if (lane == 0) {
        float mx = fmaxf(a0, a1);
        float lse = mx + logf(expf(a0 - mx) + expf(a1 - mx));
        out[p * 2 + 0] = a0 - lse;
        out[p * 2 + 1] = a1 - lse;
    }
}

// ---------------- launcher ----------------
extern "C" void kernel_launch(void* const* d_in, const int* in_sizes, int n_in,
                              void* d_out, int out_size) {
    const float* x    = (const float*)d_in[0];
    const int*   ei   = (const int*)d_in[1];
    const float* Hd   = (const float*)d_in[2];
    const int*   ui   = (const int*)d_in[3];
    const int*   ii   = (const int*)d_in[4];
    const float* Wg   = (const float*)d_in[5];
    const float* bg   = (const float*)d_in[6];
    const float* W1   = (const float*)d_in[7];
    const float* a1s  = (const float*)d_in[8];
    const float* a1d  = (const float*)d_in[9];
    const float* b1   = (const float*)d_in[10];
    const float* W2   = (const float*)d_in[11];
    const float* a2s  = (const float*)d_in[12];
    const float* a2d  = (const float*)d_in[13];
    const float* b2   = (const float*)d_in[14];
    const float* W3   = (const float*)d_in[15];
    const float* a3s  = (const float*)d_in[16];
    const float* a3d  = (const float*)d_in[17];
    const float* b3   = (const float*)d_in[18];
    const float* wd   = (const float*)d_in[19];
    const float* wr   = (const float*)d_in[20];
    const float* wdnn = (const float*)d_in[21];
    float* out = (float*)d_out;

    void *p_h0, *p_bufA, *p_bufB;
    cudaGetSymbolAddress(&p_h0, d_h0);
    cudaGetSymbolAddress(&p_bufA, d_bufA);
    cudaGetSymbolAddress(&p_bufB, d_bufB);
    float* h0   = (float*)p_h0;
    float* bufA = (float*)p_bufA;
    float* bufB = (float*)p_bufB;

    k_init<<<(NN + 255) / 256, 256>>>();
    k_gemm1<<<(128 * 512 + 255) / 256, 256>>>(wd, Hd);
    k_gemm2<<<(128 * 16 + 255) / 256, 256>>>(wr);
    k_count<<<(EE + 255) / 256, 256>>>(ei + EE);
    k_scan<<<1, 1024>>>();
    k_dis<<<(NN + 255) / 256, 256>>>();
    k_scatter<<<(ET + 255) / 256, 256>>>(ei);

    k_xw_dual<<<(NN * 16 + 255) / 256, 256>>>(x, Wg);
    k_gcn_agg<<<(NN * 16 + 255) / 256, 256>>>(bg);

    // GAT layer 1: h0[N,16] -> bufA[N,256]
    k_transform<16><<<(NN + 7) / 8, 256>>>(h0, W1, a1s, a1d);
    k_gat_agg<<<(NN * 32 + 255) / 256, 256>>>(b1, bufA);

    // GAT layer 2: bufA -> bufB
    k_transform<256><<<(NN + 7) / 8, 256>>>(bufA, W2, a2s, a2d);
    k_gat_agg<<<(NN * 32 + 255) / 256, 256>>>(b2, bufB);

    // GAT layer 3: bufB -> bufA
    k_transform<256><<<(NN + 7) / 8, 256>>>(bufB, W3, a3s, a3d);
    k_gat_agg<<<(NN * 32 + 255) / 256, 256>>>(b3, bufA);

    k_final<<<(1024 * 32 + 255) / 256, 256>>>(bufA, ui, ii, wdnn, out);
}

// round 2
// speedup vs baseline: 1.2975x; 1.2975x over previous
#include <cuda_runtime.h>
#include <cuda_bf16.h>
#include <math.h>

#define NN 50000
#define EE 800000
#define ET (EE + NN)   // edges + self loops
#define FIN0 128

// ---------------- scratch (device globals; no allocation allowed) ----------------
__device__ float d_T1[128 * 512];     // weight_d @ H_d_base
__device__ float d_M[128 * 16];       // combined dual weight
__device__ int   d_deg[NN];
__device__ int   d_rowoff[NN + 1];
__device__ int   d_cursor[NN];
__device__ float d_dis[NN];
__device__ int   d_csr[ET];
__device__ float d_xw[NN * 16];
__device__ float d_dual[NN * 16];
__device__ float d_h0[NN * 16];
__device__ float d_h1[NN * 256];      // per-layer transformed features
__device__ float d_bufA[NN * 256];
__device__ float d_bufB[NN * 256];
__device__ float d_sa[NN * 16];
__device__ float d_da[NN * 16];

// ---------------- init ----------------
__global__ void k_init() {
    int i = blockIdx.x * blockDim.x + threadIdx.x;
    if (i < NN) { d_deg[i] = 1; d_cursor[i] = 0; }   // deg starts at 1 (self loop)
}

// ---------------- combined dual weight: M = Wd @ Hd @ Wr ----------------
__global__ void k_gemm1(const float* __restrict__ wd, const float* __restrict__ hd) {
    int idx = blockIdx.x * blockDim.x + threadIdx.x;  // 128*512
    if (idx >= 128 * 512) return;
    int i = idx >> 9, j = idx & 511;
    float a = 0.f;
    for (int k = 0; k < 512; k++) a += wd[i * 512 + k] * hd[k * 512 + j];
    d_T1[idx] = a;
}

__global__ void k_gemm2(const float* __restrict__ wr) {
    int idx = blockIdx.x * blockDim.x + threadIdx.x;  // 128*16
    if (idx >= 128 * 16) return;
    int i = idx >> 4, j = idx & 15;
    float a = 0.f;
    for (int k = 0; k < 512; k++) a += d_T1[i * 512 + k] * wr[k * 16 + j];
    d_M[idx] = a;
}

// ---------------- degree count ----------------
__global__ void k_count(const int* __restrict__ dst) {
    int e = blockIdx.x * blockDim.x + threadIdx.x;
    if (e < EE) atomicAdd(&d_deg[dst[e]], 1);
}

// ---------------- warp-shuffle scan (+ fused rsqrt degree) ----------------
__global__ void k_scan() {  // one block, 1024 threads
    __shared__ int warp_sums[32];
    int t = threadIdx.x;
    const int S = 49;                       // 1024*49 >= NN
    int b0 = t * S;
    int sum = 0;
    for (int i = 0; i < S; i++) {
        int idx = b0 + i;
        if (idx < NN) sum += d_deg[idx];
    }
    int lane = t & 31, w = t >> 5;
    int v = sum;
#pragma unroll
    for (int off = 1; off < 32; off <<= 1) {
        int u = __shfl_up_sync(0xffffffffu, v, off);
        if (lane >= off) v += u;
    }
    if (lane == 31) warp_sums[w] = v;
    __syncthreads();
    if (w == 0) {
        int ws = warp_sums[lane];
#pragma unroll
        for (int off = 1; off < 32; off <<= 1) {
            int u = __shfl_up_sync(0xffffffffu, ws, off);
            if (lane >= off) ws += u;
        }
        warp_sums[lane] = ws;
    }
    __syncthreads();
    int ex = v - sum + (w > 0 ? warp_sums[w - 1] : 0);
    int run = ex;
    for (int i = 0; i < S; i++) {
        int idx = b0 + i;
        if (idx < NN) {
            int dg = d_deg[idx];
            run += dg;
            d_rowoff[idx + 1] = run;
            d_dis[idx] = rsqrtf((float)dg);
        }
    }
    if (t == 0) d_rowoff[0] = 0;
}

__global__ void k_scatter(const int* __restrict__ ei) {
    int e = blockIdx.x * blockDim.x + threadIdx.x;
    if (e >= ET) return;
    int s, dd;
    if (e < EE) { s = ei[e]; dd = ei[EE + e]; }
    else        { s = dd = e - EE; }
    int p = atomicAdd(&d_cursor[dd], 1);
    d_csr[d_rowoff[dd] + p] = s;
}

// ---------------- GCN feature transform + dual (fused) ----------------
__global__ void k_xw_dual(const float* __restrict__ x, const float* __restrict__ Wg) {
    int idx = blockIdx.x * blockDim.x + threadIdx.x;  // NN*16
    if (idx >= NN * 16) return;
    int n = idx >> 4, j = idx & 15;
    float a = 0.f, b = 0.f;
    const float* xr = x + n * FIN0;
    for (int k = 0; k < FIN0; k++) {
        float xv = xr[k];
        a += xv * Wg[k * 16 + j];
        b += xv * d_M[k * 16 + j];
    }
    d_xw[idx] = a;
    d_dual[idx] = b;
}

// ---------------- GCN aggregation + dual + elu -> h0 ----------------
__global__ void k_gcn_agg(const float* __restrict__ bg) {
    int g = (blockIdx.x * blockDim.x + threadIdx.x) >> 4;
    int j = threadIdx.x & 15;
    if (g >= NN) return;
    int beg = d_rowoff[g], end = d_rowoff[g + 1];
    float acc = 0.f;
    for (int e = beg; e < end; e++) {
        int s = d_csr[e];
        acc += d_dis[s] * d_xw[s * 16 + j];
    }
    float v = acc * d_dis[g] + bg[j] + d_dual[g * 16 + j];
    d_h0[g * 16 + j] = v > 0.f ? v : (__expf(v) - 1.f);
}

// ---------------- GAT transform: h1 = hin @ W + attention dots (register tiled) ----------------
// Block: 16 nodes x 256 cols, 128 threads. Thread: 8 nodes x 4 cols = 32 accs.
template <int FIN>
__global__ void __launch_bounds__(128, 8)
k_transform(const float* __restrict__ hin, const float* __restrict__ W,
            const float* __restrict__ asrc, const float* __restrict__ adst) {
    __shared__ float s[16][FIN];
    int tid = threadIdx.x;
    int nb = blockIdx.x * 16;
    const float4* hin4 = (const float4*)(hin + nb * FIN);
    float4* s4 = (float4*)s;
    for (int t = tid; t < 16 * FIN / 4; t += 128) s4[t] = hin4[t];
    __syncthreads();

    int cg = tid & 63;   // col group: cols [4*cg, 4*cg+4)
    int ng = tid >> 6;   // node group: nodes [8*ng, 8*ng+8)
    const float4* W4 = (const float4*)W;
    float4 acc[8];
#pragma unroll
    for (int r = 0; r < 8; r++) acc[r] = make_float4(0.f, 0.f, 0.f, 0.f);

#pragma unroll 2
    for (int k = 0; k < FIN; k++) {
        float4 w = W4[k * 64 + cg];
#pragma unroll
        for (int r = 0; r < 8; r++) {
            float sv = s[ng * 8 + r][k];
            acc[r].x += sv * w.x; acc[r].y += sv * w.y;
            acc[r].z += sv * w.z; acc[r].w += sv * w.w;
        }
    }

    float4 as4 = ((const float4*)asrc)[cg];
    float4 ad4 = ((const float4*)adst)[cg];
#pragma unroll
    for (int r = 0; r < 8; r++) {
        int n = nb + ng * 8 + r;
        ((float4*)(d_h1 + n * 256))[cg] = acc[r];
        float vs = acc[r].x * as4.x + acc[r].y * as4.y + acc[r].z * as4.z + acc[r].w * as4.w;
        float vd = acc[r].x * ad4.x + acc[r].y * ad4.y + acc[r].z * ad4.z + acc[r].w * ad4.w;
        vs += __shfl_down_sync(0xffffffffu, vs, 2, 4);
        vs += __shfl_down_sync(0xffffffffu, vs, 1, 4);
        vd += __shfl_down_sync(0xffffffffu, vd, 2, 4);
        vd += __shfl_down_sync(0xffffffffu, vd, 1, 4);
        if ((cg & 3) == 0) {
            int h = cg >> 2;   // head 0..15
            d_sa[n * 16 + h] = vs;
            d_da[n * 16 + h] = vd;
        }
    }
}

// ---------------- GAT aggregation: per-dst softmax + weighted sum + bias + elu ----------------
__global__ void k_gat_agg(const float* __restrict__ b, float* __restrict__ out) {
    int n = (blockIdx.x * blockDim.x + threadIdx.x) >> 5;
    if (n >= NN) return;
    int lane = threadIdx.x & 31;
    int hlane = lane & 15;
    float da_l = d_da[n * 16 + hlane];
    int beg = d_rowoff[n], end = d_rowoff[n + 1];

    // pass 1: per-head max; both half-warps work (2 edges per trip)
    float m = -1e30f;
    for (int e = beg + (lane >> 4); e < end; e += 2) {
        int s = d_csr[e];
        float l = d_sa[s * 16 + hlane] + da_l;
        l = l > 0.f ? l : 0.2f * l;
        m = fmaxf(m, l);
    }
    m = fmaxf(m, __shfl_xor_sync(0xffffffffu, m, 16));
    float mh = __shfl_sync(0xffffffffu, m, lane >> 1);   // lane owns head lane/2

    // pass 2: exp-sum + weighted accumulate (lane owns channels [8*lane, 8*lane+8))
    float z = 0.f;
    float acc[8];
#pragma unroll
    for (int i = 0; i < 8; i++) acc[i] = 0.f;
    for (int e = beg; e < end; e++) {
        int s = d_csr[e];
        float l = d_sa[s * 16 + hlane] + da_l;
        l = l > 0.f ? l : 0.2f * l;
        float ev = __expf(__shfl_sync(0xffffffffu, l, lane >> 1) - mh);
        z += ev;
        const float4* hp = (const float4*)(d_h1 + s * 256 + lane * 8);
        float4 v0 = hp[0], v1 = hp[1];
        acc[0] += ev * v0.x; acc[1] += ev * v0.y; acc[2] += ev * v0.z; acc[3] += ev * v0.w;
        acc[4] += ev * v1.x; acc[5] += ev * v1.y; acc[6] += ev * v1.z; acc[7] += ev * v1.w;
    }
    float invz = 1.f / (z + 1e-16f);
#pragma unroll
    for (int i = 0; i < 8; i++) {
        float v = acc[i] * invz + b[lane * 8 + i];
        out[n * 256 + lane * 8 + i] = v > 0.f ? v : (__expf(v) - 1.f);
    }
}

// ---------------- final: concat(h[user], h[item]) @ Wdnn -> log_softmax ----------------
__global__ void k_final(const float* __restrict__ h, const int* __restrict__ ui,
                        const int* __restrict__ ii, const float* __restrict__ Wd,
                        float* __restrict__ out) {
    int p = (blockIdx.x * blockDim.x + threadIdx.x) >> 5;
    if (p >= 1024) return;
    int lane = threadIdx.x & 31;
    int u = ui[p], it = ii[p];
    float a0 = 0.f, a1 = 0.f;
    for (int k = lane; k < 256; k += 32) {
        float v = h[u * 256 + k];
        a0 += v * Wd[k * 2 + 0];
        a1 += v * Wd[k * 2 + 1];
        float w = h[it * 256 + k];
        a0 += w * Wd[(256 + k) * 2 + 0];
        a1 += w * Wd[(256 + k) * 2 + 1];
    }
#pragma unroll
    for (int off = 16; off >= 1; off >>= 1) {
        a0 += __shfl_down_sync(0xffffffffu, a0, off);
        a1 += __shfl_down_sync(0xffffffffu, a1, off);
    }
    if (lane == 0) {
        float mx = fmaxf(a0, a1);
        float lse = mx + __logf(__expf(a0 - mx) + __expf(a1 - mx));
        out[p * 2 + 0] = a0 - lse;
        out[p * 2 + 1] = a1 - lse;
    }
}

// ---------------- launcher ----------------
extern "C" void kernel_launch(void* const* d_in, const int* in_sizes, int n_in,
                              void* d_out, int out_size) {
    const float* x    = (const float*)d_in[0];
    const int*   ei   = (const int*)d_in[1];
    const float* Hd   = (const float*)d_in[2];
    const int*   ui   = (const int*)d_in[3];
    const int*   ii   = (const int*)d_in[4];
    const float* Wg   = (const float*)d_in[5];
    const float* bg   = (const float*)d_in[6];
    const float* W1   = (const float*)d_in[7];
    const float* a1s  = (const float*)d_in[8];
    const float* a1d  = (const float*)d_in[9];
    const float* b1   = (const float*)d_in[10];
    const float* W2   = (const float*)d_in[11];
    const float* a2s  = (const float*)d_in[12];
    const float* a2d  = (const float*)d_in[13];
    const float* b2   = (const float*)d_in[14];
    const float* W3   = (const float*)d_in[15];
    const float* a3s  = (const float*)d_in[16];
    const float* a3d  = (const float*)d_in[17];
    const float* b3   = (const float*)d_in[18];
    const float* wd   = (const float*)d_in[19];
    const float* wr   = (const float*)d_in[20];
    const float* wdnn = (const float*)d_in[21];
    float* out = (float*)d_out;

    void *p_h0, *p_bufA, *p_bufB;
    cudaGetSymbolAddress(&p_h0, d_h0);
    cudaGetSymbolAddress(&p_bufA, d_bufA);
    cudaGetSymbolAddress(&p_bufB, d_bufB);
    float* h0   = (float*)p_h0;
    float* bufA = (float*)p_bufA;
    float* bufB = (float*)p_bufB;

    k_init<<<(NN + 255) / 256, 256>>>();
    k_gemm1<<<(128 * 512 + 255) / 256, 256>>>(wd, Hd);
    k_gemm2<<<(128 * 16 + 255) / 256, 256>>>(wr);
    k_count<<<(EE + 255) / 256, 256>>>(ei + EE);
    k_scan<<<1, 1024>>>();
    k_scatter<<<(ET + 255) / 256, 256>>>(ei);

    k_xw_dual<<<(NN * 16 + 255) / 256, 256>>>(x, Wg);
    k_gcn_agg<<<(NN * 16 + 255) / 256, 256>>>(bg);

    // GAT layer 1: h0[N,16] -> bufA[N,256]
    k_transform<16><<<NN / 16, 128>>>(h0, W1, a1s, a1d);
    k_gat_agg<<<(NN * 32 + 255) / 256, 256>>>(b1, bufA);

    // GAT layer 2: bufA -> bufB
    k_transform<256><<<NN / 16, 128>>>(bufA, W2, a2s, a2d);
    k_gat_agg<<<(NN * 32 + 255) / 256, 256>>>(b2, bufB);

    // GAT layer 3: bufB -> bufA
    k_transform<256><<<NN / 16, 128>>>(bufB, W3, a3s, a3d);
    k_gat_agg<<<(NN * 32 + 255) / 256, 256>>>(b3, bufA);

    k_final<<<(1024 * 32 + 255) / 256, 256>>>(bufA, ui, ii, wdnn, out);
}